// round 11
// baseline (speedup 1.0000x reference)
#include <cuda_runtime.h>
#include <cstdint>
#include <math.h>

#define KDIM 3072
#define NBC  4096
#define NMID 1024

// smem stage geometry (floats): A 128x16 @ pitch20 = 2560, B 16x128 @ pitch136 = 2176
#define APITCH 20
#define BPITCH 136
#define AFLOATS 2560
#define STAGEF  4736          // floats per stage
#define NSTAGE  4
#define SMEMB   (STAGEF * NSTAGE * 4)   // 75776 bytes

__device__ float g_H1[(size_t)3072 * 4096];  // depth-0 GLU output

__device__ __forceinline__ uint32_t s2u(const void* p) {
    uint32_t a;
    asm("{\n.reg .u64 t;\ncvta.to.shared.u64 t,%1;\ncvt.u32.u64 %0,t;\n}" : "=r"(a) : "l"(p));
    return a;
}
__device__ __forceinline__ void ldsm4(uint32_t* r, uint32_t addr) {
    asm volatile("ldmatrix.sync.aligned.m8n8.x4.shared.b16 {%0,%1,%2,%3},[%4];"
                 : "=r"(r[0]), "=r"(r[1]), "=r"(r[2]), "=r"(r[3]) : "r"(addr));
}
__device__ __forceinline__ void mma8(float* d, const uint32_t* a, const uint32_t* b) {
    asm volatile("mma.sync.aligned.m16n8k8.row.col.f32.tf32.tf32.f32 "
                 "{%0,%1,%2,%3},{%4,%5,%6,%7},{%8,%9},{%0,%1,%2,%3};"
                 : "+f"(d[0]), "+f"(d[1]), "+f"(d[2]), "+f"(d[3])
                 : "r"(a[0]), "r"(a[1]), "r"(a[2]), "r"(a[3]), "r"(b[0]), "r"(b[1]));
}
__device__ __forceinline__ void cpasync16(uint32_t dst, const void* src) {
    asm volatile("cp.async.cg.shared.global [%0],[%1],16;" :: "r"(dst), "l"(src));
}

// ---------------------------------------------------------------------------
// D[v,bc] = sum_w Ag[v,w]*Bg[w,bc] via mma.sync tf32 + fused GLU (+max).
// BM=BN=128, BK=16, 4-stage cp.async pipeline (A and B), B k-major in smem
// (no transpose; B fragments via conflict-free LDS.32).
// ---------------------------------------------------------------------------
__global__ __launch_bounds__(256, 2) void mma_glu_k(
    const float* __restrict__ Ag,     // (Mrows, 3072) band base
    const float* __restrict__ Bg,     // (3072, 4096)
    const float* __restrict__ W,      // (128, 64)
    const float* __restrict__ bias,   // (128,)
    const float* __restrict__ maxsrc, // nullptr or aligned with out
    float* __restrict__ out)          // (Mrows, 4096)
{
    extern __shared__ float smem[];
    const uint32_t smb = s2u(smem);
    const int tid = threadIdx.x, lane = tid & 31, wid = tid >> 5;
    const int bx = blockIdx.x, by = blockIdx.y;
    const int wm = wid >> 2, wn = wid & 3;   // warp grid 2 (m) x 4 (n)

    // A ldmatrix addressing (validated in R9): lane bit3 -> +8 rows, bit4 -> +16B
    const int arow = (lane & 7) + ((lane >> 3) & 1) * 8;
    const int ab16 = ((lane >> 4) & 1) * 16;
    uint32_t aoff[4];
    #pragma unroll
    for (int g = 0; g < 4; g++)
        aoff[g] = (wm * 64 + g * 16 + arow) * (APITCH * 4) + ab16;

    // B fragment LDS float-offset WITHIN STAGE (includes AFLOATS base!):
    // b0 at [k=lane&3][n = wn*32 + (lane>>2)], b1 at k+4.
    const uint32_t bbase = AFLOATS + (lane & 3) * BPITCH + wn * 32 + (lane >> 2);

    // cp.async loaders
    const int arw = tid >> 1;                  // A row 0..127
    const float* aSrc = Ag + (size_t)(by * 128 + arw) * KDIM + (tid & 1) * 8;
    const uint32_t aDst = arw * APITCH + (tid & 1) * 8;          // float idx
    const int bk = tid >> 4, bj = tid & 15;    // B row(k) 0..15, col-block 0..15
    const float* bSrc = Bg + (size_t)bx * 128 + bj * 8;
    const uint32_t bDst = AFLOATS + bk * BPITCH + bj * 8;        // float idx

    auto issue = [&](int c) {   // stage slot c % NSTAGE; always commits a group
        if (c < 192) {
            const uint32_t sb = smb + (c & (NSTAGE - 1)) * (STAGEF * 4);
            const float* as = aSrc + c * 16;
            cpasync16(sb + aDst * 4, as);
            cpasync16(sb + aDst * 4 + 16, as + 4);
            const float* bs = bSrc + (size_t)(c * 16 + bk) * NBC;
            cpasync16(sb + bDst * 4, bs);
            cpasync16(sb + bDst * 4 + 16, bs + 4);
        }
        asm volatile("cp.async.commit_group;");
    };

    float acc[4][4][4] = {};

    issue(0); issue(1); issue(2);

    for (int c = 0; c < 192; c++) {
        asm volatile("cp.async.wait_group 2;");
        __syncthreads();
        issue(c + 3);

        const uint32_t sb = smb + (c & (NSTAGE - 1)) * (STAGEF * 4);
        const float* bReg = smem + (c & (NSTAGE - 1)) * STAGEF + bbase;
        uint32_t a[4][4], b[4][2];
        #pragma unroll
        for (int ks = 0; ks < 2; ks++) {
            #pragma unroll
            for (int g = 0; g < 4; g++) ldsm4(a[g], sb + aoff[g] + ks * 32);
            const float* bp = bReg + ks * 8 * BPITCH;
            #pragma unroll
            for (int f = 0; f < 4; f++) {
                b[f][0] = __float_as_uint(bp[f * 8]);
                b[f][1] = __float_as_uint(bp[f * 8 + 4 * BPITCH]);
            }
            #pragma unroll
            for (int g = 0; g < 4; g++)
                #pragma unroll
                for (int f = 0; f < 4; f++)
                    mma8(acc[g][f], a[g], b[f]);
        }
    }
    __syncthreads();

    // ---------------- fused GLU epilogue, 4 chunks of 32 tile-rows ----------
    // acc layout: c0,c1 = (row=lane>>2, n=(lane&3)*2+{0,1}), c2,c3 = row+8.
    float* gs = smem;                 // [p2 = local_row*2 + b2][c], pitch 68
    const int pair = tid >> 2;        // (v_local, b2) pair within chunk
    const int h0 = (tid & 3) << 4;    // 16 h per thread
    const int vLoc = pair >> 1, b2r = pair & 1;

    #pragma unroll 1
    for (int ch = 0; ch < 4; ch++) {
        if (wm == (ch >> 1)) {
            #pragma unroll
            for (int gg = 0; gg < 2; gg++) {
                const int g = (ch & 1) * 2 + gg;
                #pragma unroll
                for (int f = 0; f < 4; f++) {
                    const int n0 = wn * 32 + f * 8 + (lane & 3) * 2;
                    const int b2 = n0 >> 6, cc = n0 & 63;
                    const int lr = gg * 16 + (lane >> 2);
                    *(float2*)&gs[(lr * 2 + b2) * 68 + cc] =
                        make_float2(acc[g][f][0], acc[g][f][1]);
                    *(float2*)&gs[((lr + 8) * 2 + b2) * 68 + cc] =
                        make_float2(acc[g][f][2], acc[g][f][3]);
                }
            }
        }
        __syncthreads();

        const float* grow = &gs[pair * 68];
        const size_t orow = (size_t)((by << 7) + (ch << 5) + vLoc) * NBC
                          + (bx << 7) + (b2r << 6);
        #pragma unroll 4
        for (int hq = 0; hq < 4; hq++) {
            float v4[4];
            #pragma unroll
            for (int hs = 0; hs < 4; hs++) {
                const int h = h0 + hq * 4 + hs;
                float accL = __ldg(&bias[h]);
                float accR = __ldg(&bias[h + 64]);
                const float4* wl = (const float4*)(W + h * 64);
                const float4* wr = (const float4*)(W + (h + 64) * 64);
                #pragma unroll
                for (int c4 = 0; c4 < 16; c4++) {
                    float4 g = *(const float4*)(grow + c4 * 4);
                    float4 a = __ldg(wl + c4), r = __ldg(wr + c4);
                    accL += a.x * g.x + a.y * g.y + a.z * g.z + a.w * g.w;
                    accR += r.x * g.x + r.y * g.y + r.z * g.z + r.w * g.w;
                }
                v4[hs] = __fdividef(accL, 1.0f + __expf(-accR));
            }
            if (maxsrc) {
                float4 m = *(const float4*)(maxsrc + orow + h0 + hq * 4);
                v4[0] = fmaxf(v4[0], m.x); v4[1] = fmaxf(v4[1], m.y);
                v4[2] = fmaxf(v4[2], m.z); v4[3] = fmaxf(v4[3], m.w);
            }
            *(float4*)(out + orow + h0 + hq * 4) = make_float4(v4[0], v4[1], v4[2], v4[3]);
        }
        __syncthreads();
    }
}

extern "C" void kernel_launch(void* const* d_in, const int* in_sizes, int n_in,
                              void* d_out, int out_size)
{
    const float* x  = (const float*)d_in[0];
    const float* A  = (const float*)d_in[1];
    const float* W0 = (const float*)d_in[2];
    const float* b0 = (const float*)d_in[3];
    const float* W1 = (const float*)d_in[4];
    const float* b1 = (const float*)d_in[5];
    float* out = (float*)d_out;

    float* H1 = nullptr;
    cudaGetSymbolAddress((void**)&H1, g_H1);
    if (!H1) return;

    cudaFuncSetAttribute(mma_glu_k, cudaFuncAttributeMaxDynamicSharedMemorySize, SMEMB);

    mma_glu_k<<<dim3(32, 24), 256, SMEMB>>>(A, x, W0, b0, nullptr, H1);
    mma_glu_k<<<dim3(32, 8), 256, SMEMB>>>(A + (size_t)NMID * KDIM, H1, W1, b1,
                                           H1 + (size_t)NMID * NBC, out);
}